// round 16
// baseline (speedup 1.0000x reference)
#include <cuda_runtime.h>
#include <cuda_bf16.h>
#include <cuda_fp16.h>
#include <cstdint>

#define NBATCH 32
#define TLEN 256
#define VNODES 19
#define DM 256
#define DK 768
#define NT (NBATCH*TLEN)        // 8192
#define MROWS (NT*VNODES)       // 155648
#define MTILES (MROWS/128)      // 1216

typedef unsigned long long u64;

// scratch (device globals: allocation-free)
__device__ __half g_y[(size_t)MROWS * DK];              // GEMM output, fp16, ~239MB
__device__ __half g_z[(size_t)MROWS * DM];              // pre-activation z, fp16, ~80MB
__device__ __half g_bh[DK*256];                         // W^T fp16, swizzled n-major
__device__ float g_An[3*8*VNODES*20];                   // normalized adjacency (padded)
__device__ float g_stats[2*DK];
__device__ float g_sb[2*DK];
__device__ float g_stats1[2*DM];
__device__ float g_sb1[2*DM];

__device__ __forceinline__ u64 pack2(float x, float y){
    u64 r; asm("mov.b64 %0, {%1,%2};" : "=l"(r) : "f"(x), "f"(y)); return r;
}
__device__ __forceinline__ void unpack2(u64 v, float &x, float &y){
    asm("mov.b64 {%0,%1}, %2;" : "=f"(x), "=f"(y) : "l"(v));
}
__device__ __forceinline__ void ffma2(u64 &d, u64 a, u64 b){
    asm("fma.rn.f32x2 %0, %1, %2, %0;" : "+l"(d) : "l"(a), "l"(b));
}
__device__ __forceinline__ uint32_t smem_u32(const void* p){
    uint32_t a;
    asm("{ .reg .u64 t; cvta.to.shared.u64 t, %1; cvt.u32.u64 %0, t; }" : "=r"(a) : "l"(p));
    return a;
}
__device__ __forceinline__ void cpa16(uint32_t d, const void* s){
    asm volatile("cp.async.cg.shared.global [%0], [%1], 16;" :: "r"(d), "l"(s));
}
#define CPA_COMMIT() asm volatile("cp.async.commit_group;" ::: "memory")
#define CPA_WAIT0()  asm volatile("cp.async.wait_group 0;" ::: "memory")
#define CPA_WAIT1()  asm volatile("cp.async.wait_group 1;" ::: "memory")

#define LDSM4(r0,r1,r2,r3,addr) \
    asm volatile("ldmatrix.sync.aligned.m8n8.x4.shared.b16 {%0,%1,%2,%3}, [%4];" \
                 : "=r"(r0),"=r"(r1),"=r"(r2),"=r"(r3) : "r"(addr))

#define MMAF16(c,a,b0,b1) \
    asm volatile("mma.sync.aligned.m16n8k16.row.col.f32.f16.f16.f32 " \
                 "{%0,%1,%2,%3},{%4,%5,%6,%7},{%8,%9},{%0,%1,%2,%3};" \
                 : "+f"((c)[0]),"+f"((c)[1]),"+f"((c)[2]),"+f"((c)[3]) \
                 : "r"((a)[0]),"r"((a)[1]),"r"((a)[2]),"r"((a)[3]),"r"(b0),"r"(b1))

// ---------------------------------------------------------------------------
__global__ void k_prep(const float* __restrict__ para) {
    int tid = threadIdx.x;
    for (int i = tid; i < 2*DK; i += blockDim.x) g_stats[i] = 0.f;
    for (int i = tid; i < 2*DM; i += blockDim.x) g_stats1[i] = 0.f;
    if (tid < 3*8*VNODES) {
        const float* src = para + tid*VNODES;
        float ss = 0.f;
        #pragma unroll
        for (int w = 0; w < VNODES; w++) ss += src[w]*src[w];
        float inv = 1.0f / (sqrtf(ss) + 1e-4f);
        float* dst = g_An + tid*20;
        #pragma unroll
        for (int w = 0; w < VNODES; w++) dst[w] = src[w]*inv;
        dst[VNODES] = 0.f;
    }
}

// ---------------------------------------------------------------------------
// Convert W to fp16, transposed n-major [col][k], pre-swizzled.
// ---------------------------------------------------------------------------
__global__ void k_conv_w(const float* __restrict__ W) {
    int idx = blockIdx.x * blockDim.x + threadIdx.x;    // 768*32 = 24576
    if (idx >= DK*32) return;
    int c   = idx & 31;
    int col = idx >> 5;
    int k0 = c*8;
    uint32_t h[4];
    #pragma unroll
    for (int j = 0; j < 4; j++) {
        __half a = __float2half_rn(W[(size_t)(k0 + 2*j    )*DK + col]);
        __half b = __float2half_rn(W[(size_t)(k0 + 2*j + 1)*DK + col]);
        h[j] = (uint32_t)__half_as_ushort(a) | ((uint32_t)__half_as_ushort(b) << 16);
    }
    size_t dst = (size_t)col*512 + (size_t)((c ^ (col & 7)) << 4);
    *(uint4*)((char*)g_bh + dst) = make_uint4(h[0], h[1], h[2], h[3]);
}

// ---------------------------------------------------------------------------
// Single-pass fp16 tensor-core GEMM: y = X @ W, fp32 accumulate.
// 1216 CTAs x 128 rows; 512 threads = 4x4 warps, warp tile 32x32.
// 6 N-tiles of 128, cp.async double-buffered B tiles (64KB each).
// smem: A 64KB | Btile[2] x 64KB = 192KB
// ---------------------------------------------------------------------------
#define GEMM_THREADS 512
#define OFF_B   65536u
#define B_TILE  65536u
#define SMEM_GEMM (65536 + 2*65536)   // 196608 B

__global__ void __launch_bounds__(GEMM_THREADS) k_gemm_mma(const float* __restrict__ X) {
    extern __shared__ char sm[];
    const int tid = threadIdx.x, lane = tid & 31, wid = tid >> 5;   // 0..15
    const int wm = wid & 3, wn = wid >> 2;     // 4 row-warps x 4 col-warps
    const size_t bm = blockIdx.x;

    const uint32_t sA = smem_u32(sm);

    // prologue: B tile 0 via cp.async (in flight), A converted inline
    #pragma unroll
    for (int u = 0; u < 8; u++) {
        int i = tid + u*512;                    // 0..4095
        cpa16(sA + OFF_B + (uint32_t)i*16u, (const char*)g_bh + (size_t)i*16);
    }
    CPA_COMMIT();
    {
        const float4* Xb = (const float4*)(X + bm*32768);
        #pragma unroll
        for (int u = 0; u < 16; u++) {
            int i = tid + u*512;
            int rr = i >> 6, c4 = i & 63;
            float4 v = Xb[i];
            union { __half h[4]; u64 u2; } hp;
            hp.h[0] = __float2half_rn(v.x);
            hp.h[1] = __float2half_rn(v.y);
            hp.h[2] = __float2half_rn(v.z);
            hp.h[3] = __float2half_rn(v.w);
            uint32_t base = (uint32_t)rr*512u
                          + ((((uint32_t)(c4 >> 1)) ^ (uint32_t)(rr & 7)) << 4)
                          + (uint32_t)((c4 & 1) * 8);
            *(u64*)(sm + base) = hp.u2;
        }
    }
    CPA_WAIT0();
    __syncthreads();

    const int rA    = wm*32 + (lane & 15);
    const int koffA = lane >> 4;
    const int rB    = wn*32 + (lane & 7) + ((lane >> 4) << 3);
    const int koffB = (lane >> 3) & 1;
    const int r0    = wm*32 + (lane >> 2);
    const uint32_t axor = (uint32_t)(rA & 7), bxor = (uint32_t)(rB & 7);
    const uint32_t aB = sA + (uint32_t)rA * 512;

    for (int nt = 0; nt < 6; nt++) {
        const int buf = nt & 1;
        // prefetch next B tile into the other buffer
        if (nt + 1 < 6) {
            uint32_t dst = sA + OFF_B + (uint32_t)(buf ^ 1) * B_TILE;
            const char* src = (const char*)g_bh + (size_t)(nt + 1) * B_TILE;
            #pragma unroll
            for (int u = 0; u < 8; u++) {
                int i = tid + u*512;
                cpa16(dst + (uint32_t)i*16u, src + (size_t)i*16);
            }
            CPA_COMMIT();
        }

        float acc[2][4][4];
        #pragma unroll
        for (int mi = 0; mi < 2; mi++)
            #pragma unroll
            for (int ni = 0; ni < 4; ni++)
                #pragma unroll
                for (int j = 0; j < 4; j++) acc[mi][ni][j] = 0.f;

        const uint32_t bB = sA + OFF_B + (uint32_t)buf * B_TILE + (uint32_t)rB * 512;

        #pragma unroll
        for (int kc = 0; kc < 16; kc++) {
            uint32_t ach = (((uint32_t)(kc*2 + koffA)) ^ axor) << 4;
            uint32_t bch = (((uint32_t)(kc*2 + koffB)) ^ bxor) << 4;
            uint32_t a0[4], a1[4], b0[4], b1[4];
            LDSM4(a0[0], a0[1], a0[2], a0[3], aB + ach);
            LDSM4(a1[0], a1[1], a1[2], a1[3], aB + 8192 + ach);
            LDSM4(b0[0], b0[1], b0[2], b0[3], bB + bch);
            LDSM4(b1[0], b1[1], b1[2], b1[3], bB + 8192 + bch);
            MMAF16(acc[0][0], a0, b0[0], b0[1]);
            MMAF16(acc[0][1], a0, b0[2], b0[3]);
            MMAF16(acc[0][2], a0, b1[0], b1[1]);
            MMAF16(acc[0][3], a0, b1[2], b1[3]);
            MMAF16(acc[1][0], a1, b0[0], b0[1]);
            MMAF16(acc[1][1], a1, b0[2], b0[3]);
            MMAF16(acc[1][2], a1, b1[0], b1[1]);
            MMAF16(acc[1][3], a1, b1[2], b1[3]);
        }

        // epilogue: write g_y (fp16) + BN stats (fp32, exact)
        #pragma unroll
        for (int mi = 0; mi < 2; mi++) {
            #pragma unroll
            for (int ni = 0; ni < 4; ni++) {
                int cb = wn*32 + ((ni >> 1) << 4) + ((ni & 1) << 3) + ((lane & 3) << 1);
                __half* p = g_y + (bm*128 + r0 + mi*16)*DK + nt*128 + cb;
                *(__half2*)p = __floats2half2_rn(acc[mi][ni][0], acc[mi][ni][1]);
                *(__half2*)(p + (size_t)8*DK) = __floats2half2_rn(acc[mi][ni][2], acc[mi][ni][3]);
            }
        }
        #pragma unroll
        for (int ni = 0; ni < 4; ni++) {
            float s0 = acc[0][ni][0] + acc[0][ni][2] + acc[1][ni][0] + acc[1][ni][2];
            float s1 = acc[0][ni][1] + acc[0][ni][3] + acc[1][ni][1] + acc[1][ni][3];
            float q0 = acc[0][ni][0]*acc[0][ni][0] + acc[0][ni][2]*acc[0][ni][2]
                     + acc[1][ni][0]*acc[1][ni][0] + acc[1][ni][2]*acc[1][ni][2];
            float q1 = acc[0][ni][1]*acc[0][ni][1] + acc[0][ni][3]*acc[0][ni][3]
                     + acc[1][ni][1]*acc[1][ni][1] + acc[1][ni][3]*acc[1][ni][3];
            #pragma unroll
            for (int off = 4; off < 32; off <<= 1) {
                s0 += __shfl_xor_sync(0xFFFFFFFFu, s0, off);
                s1 += __shfl_xor_sync(0xFFFFFFFFu, s1, off);
                q0 += __shfl_xor_sync(0xFFFFFFFFu, q0, off);
                q1 += __shfl_xor_sync(0xFFFFFFFFu, q1, off);
            }
            if (lane < 4) {
                int col = nt*128 + wn*32 + ((ni >> 1) << 4) + ((ni & 1) << 3) + lane*2;
                atomicAdd(&g_stats[col],         s0);
                atomicAdd(&g_stats[col + 1],     s1);
                atomicAdd(&g_stats[DK + col],    q0);
                atomicAdd(&g_stats[DK + col+1],  q1);
            }
        }

        if (nt + 1 < 6) CPA_WAIT0();
        __syncthreads();
    }
}

// ---------------------------------------------------------------------------
__global__ void k_fin_bn(const float* __restrict__ gamma, const float* __restrict__ beta) {
    int d = threadIdx.x;
    float inv = 1.0f / (float)MROWS;
    float mean = g_stats[d] * inv;
    float var  = g_stats[DK + d] * inv - mean*mean;
    float sc = gamma[d] * rsqrtf(var + 1e-5f);
    g_sb[d]      = sc;
    g_sb[DK + d] = beta[d] - mean*sc;
}

// ---------------------------------------------------------------------------
// Per-(n,t): z[c,w] = sum_{k,v} yhat[v, k*256+c] * An[k, c%8, v, w] + x[n,t,w,c]
// 4 tiles per block, cp.async DOUBLE-BUFFERED fp16 y tiles.
// Writes pre-activation z as fp16 to g_z (half the store traffic).
// smem: ybuf[2] x 29184B + A 36480B = 94848 B -> 2 CTAs/SM
// ---------------------------------------------------------------------------
#define YTILE_E (VNODES*DK)          // 14592 elements
#define YTILE_B (YTILE_E*2)          // 29184 bytes (fp16)
#define SMEM_CONTRACT (2*YTILE_B + 3*8*VNODES*20*4)   // 94848 B

__global__ void __launch_bounds__(256, 2) k_contract(const float* __restrict__ X) {
    extern __shared__ char smc[];
    float* Ash = (float*)(smc + 2*YTILE_B);
    const int tid = threadIdx.x;
    const size_t nt0 = (size_t)blockIdx.x * 4;
    const uint32_t sb = smem_u32(smc);

    for (int i = tid; i < 3*8*VNODES*20; i += 256) Ash[i] = g_An[i];
    {
        const char* src = (const char*)(g_y + nt0 * YTILE_E);
        for (int i = tid; i < YTILE_B/16; i += 256)
            cpa16(sb + (uint32_t)i*16u, src + (size_t)i*16);
        CPA_COMMIT();
    }

    const int c = tid, g = c & 7;
    float sc[3], of[3];
    #pragma unroll
    for (int k = 0; k < 3; k++) {
        sc[k] = g_sb[k*DM + c];
        of[k] = g_sb[DK + k*DM + c];
    }

    float s_tot = 0.f, q_tot = 0.f;

    for (int r = 0; r < 4; r++) {
        const size_t nt = nt0 + r;
        if (r < 3) {
            const char* src = (const char*)(g_y + (nt + 1) * YTILE_E);
            uint32_t dst = sb + (((r + 1) & 1) ? (uint32_t)YTILE_B : 0u);
            for (int i = tid; i < YTILE_B/16; i += 256)
                cpa16(dst + (uint32_t)i*16u, src + (size_t)i*16);
            CPA_COMMIT();
            CPA_WAIT1();
        } else {
            CPA_WAIT0();
        }
        __syncthreads();

        const __half* ysh = (const __half*)(smc + ((r & 1) ? YTILE_B : 0));

        u64 acc[10];
        #pragma unroll
        for (int p = 0; p < 10; p++) acc[p] = 0ull;
        #pragma unroll
        for (int k = 0; k < 3; k++) {
            const u64* Ab = (const u64*)(Ash + (size_t)((k*8 + g)*VNODES)*20);
            #pragma unroll
            for (int v = 0; v < VNODES; v++) {
                float yv = fmaf(__half2float(ysh[v*DK + k*DM + c]), sc[k], of[k]);
                u64 yp = pack2(yv, yv);
                const u64* ar = Ab + v*10;
                #pragma unroll
                for (int p = 0; p < 10; p++) ffma2(acc[p], yp, ar[p]);
            }
        }

        float z[20];
        #pragma unroll
        for (int p = 0; p < 10; p++) unpack2(acc[p], z[2*p], z[2*p+1]);

        const float* xb = X + nt * (size_t)(VNODES*DM) + c;
        __half* zb = g_z + nt * (size_t)(VNODES*DM) + c;
        #pragma unroll
        for (int w = 0; w < VNODES; w++) {
            float zv = z[w] + xb[(size_t)w * DM];
            s_tot += zv; q_tot += zv*zv;
            zb[(size_t)w * DM] = __float2half_rn(zv);
        }
        __syncthreads();
    }
    atomicAdd(&g_stats1[c], s_tot);
    atomicAdd(&g_stats1[DM + c], q_tot);
}

__global__ void k_fin_bn1(const float* __restrict__ gamma, const float* __restrict__ beta) {
    int d = threadIdx.x;
    float inv = 1.0f / (float)MROWS;
    float mean = g_stats1[d] * inv;
    float var  = g_stats1[DM + d] * inv - mean*mean;
    float sc = gamma[d] * rsqrtf(var + 1e-5f);
    g_sb1[d]      = sc;
    g_sb1[DM + d] = beta[d] - mean*sc;
}

// ---------------------------------------------------------------------------
// BN1 affine + ReLU: read fp16 z, write fp32 out. 8 elements per thread-iter.
// ---------------------------------------------------------------------------
__global__ void k_relu(float* __restrict__ out) {
    size_t total8 = (size_t)MROWS * DM / 8;
    const uint4* z8 = (const uint4*)g_z;
    for (size_t i = (size_t)blockIdx.x * blockDim.x + threadIdx.x; i < total8;
         i += (size_t)gridDim.x * blockDim.x) {
        int c = (int)(i & 31) * 8;
        uint4 zv = z8[i];
        const uint32_t zr[4] = {zv.x, zv.y, zv.z, zv.w};
        float ov[8];
        #pragma unroll
        for (int j = 0; j < 4; j++) {
            __half2 h = *(const __half2*)&zr[j];
            float2 f = __half22float2(h);
            ov[2*j]   = fmaxf(fmaf(f.x, g_sb1[c + 2*j],     g_sb1[DM + c + 2*j]),     0.f);
            ov[2*j+1] = fmaxf(fmaf(f.y, g_sb1[c + 2*j + 1], g_sb1[DM + c + 2*j + 1]), 0.f);
        }
        float4* o4 = (float4*)(out + i*8);
        o4[0] = make_float4(ov[0], ov[1], ov[2], ov[3]);
        o4[1] = make_float4(ov[4], ov[5], ov[6], ov[7]);
    }
}

extern "C" void kernel_launch(void* const* d_in, const int* in_sizes, int n_in,
                              void* d_out, int out_size) {
    const float* x    = (const float*)d_in[0];
    const float* para = (const float*)d_in[1];
    const float* W    = (const float*)d_in[2];
    // d_in[3] linear_bias: cancels under training-mode BN (mean subtraction)
    const float* bng  = (const float*)d_in[4];
    const float* bnb  = (const float*)d_in[5];
    const float* bn1g = (const float*)d_in[6];
    const float* bn1b = (const float*)d_in[7];
    float* out = (float*)d_out;

    cudaFuncSetAttribute(k_contract, cudaFuncAttributeMaxDynamicSharedMemorySize,
                         SMEM_CONTRACT);
    cudaFuncSetAttribute(k_gemm_mma, cudaFuncAttributeMaxDynamicSharedMemorySize,
                         SMEM_GEMM);

    k_prep<<<1, 512>>>(para);
    k_conv_w<<<96, 256>>>(W);
    k_gemm_mma<<<MTILES, GEMM_THREADS, SMEM_GEMM>>>(x);
    k_fin_bn<<<1, DK>>>(bng, bnb);
    k_contract<<<NT/4, 256, SMEM_CONTRACT>>>(x);
    k_fin_bn1<<<1, DM>>>(bn1g, bn1b);
    k_relu<<<2048, 256>>>(out);
}

// round 17
// speedup vs baseline: 1.0705x; 1.0705x over previous
#include <cuda_runtime.h>
#include <cuda_bf16.h>
#include <cuda_fp16.h>
#include <cstdint>

#define NBATCH 32
#define TLEN 256
#define VNODES 19
#define DM 256
#define DK 768
#define NT (NBATCH*TLEN)        // 8192
#define MROWS (NT*VNODES)       // 155648
#define MTILES (MROWS/128)      // 1216

typedef unsigned long long u64;

// scratch (device globals: allocation-free)
__device__ __half g_y[(size_t)MROWS * DK];              // GEMM output, fp16, ~239MB
__device__ __half g_z[(size_t)MROWS * DM];              // pre-activation z, fp16, ~80MB
__device__ __half g_bh[DK*256];                         // W^T fp16, swizzled n-major
__device__ float g_An[3*8*VNODES*20];                   // normalized adjacency (padded)
__device__ float g_stats[2*DK];
__device__ float g_sb[2*DK];
__device__ float g_stats1[2*DM];
__device__ float g_sb1[2*DM];

__device__ __forceinline__ u64 pack2(float x, float y){
    u64 r; asm("mov.b64 %0, {%1,%2};" : "=l"(r) : "f"(x), "f"(y)); return r;
}
__device__ __forceinline__ void unpack2(u64 v, float &x, float &y){
    asm("mov.b64 {%0,%1}, %2;" : "=f"(x), "=f"(y) : "l"(v));
}
__device__ __forceinline__ void ffma2(u64 &d, u64 a, u64 b){
    asm("fma.rn.f32x2 %0, %1, %2, %0;" : "+l"(d) : "l"(a), "l"(b));
}
__device__ __forceinline__ uint32_t smem_u32(const void* p){
    uint32_t a;
    asm("{ .reg .u64 t; cvta.to.shared.u64 t, %1; cvt.u32.u64 %0, t; }" : "=r"(a) : "l"(p));
    return a;
}
__device__ __forceinline__ void cpa16(uint32_t d, const void* s){
    asm volatile("cp.async.cg.shared.global [%0], [%1], 16;" :: "r"(d), "l"(s));
}
#define CPA_COMMIT() asm volatile("cp.async.commit_group;" ::: "memory")
#define CPA_WAIT0()  asm volatile("cp.async.wait_group 0;" ::: "memory")
#define CPA_WAIT1()  asm volatile("cp.async.wait_group 1;" ::: "memory")

#define LDSM4(r0,r1,r2,r3,addr) \
    asm volatile("ldmatrix.sync.aligned.m8n8.x4.shared.b16 {%0,%1,%2,%3}, [%4];" \
                 : "=r"(r0),"=r"(r1),"=r"(r2),"=r"(r3) : "r"(addr))

#define MMAF16(c,a,b0,b1) \
    asm volatile("mma.sync.aligned.m16n8k16.row.col.f32.f16.f16.f32 " \
                 "{%0,%1,%2,%3},{%4,%5,%6,%7},{%8,%9},{%0,%1,%2,%3};" \
                 : "+f"((c)[0]),"+f"((c)[1]),"+f"((c)[2]),"+f"((c)[3]) \
                 : "r"((a)[0]),"r"((a)[1]),"r"((a)[2]),"r"((a)[3]),"r"(b0),"r"(b1))

// ---------------------------------------------------------------------------
__global__ void k_prep(const float* __restrict__ para) {
    int tid = threadIdx.x;
    for (int i = tid; i < 2*DK; i += blockDim.x) g_stats[i] = 0.f;
    for (int i = tid; i < 2*DM; i += blockDim.x) g_stats1[i] = 0.f;
    if (tid < 3*8*VNODES) {
        const float* src = para + tid*VNODES;
        float ss = 0.f;
        #pragma unroll
        for (int w = 0; w < VNODES; w++) ss += src[w]*src[w];
        float inv = 1.0f / (sqrtf(ss) + 1e-4f);
        float* dst = g_An + tid*20;
        #pragma unroll
        for (int w = 0; w < VNODES; w++) dst[w] = src[w]*inv;
        dst[VNODES] = 0.f;
    }
}

// ---------------------------------------------------------------------------
// Convert W to fp16, transposed n-major [col][k], pre-swizzled.
// ---------------------------------------------------------------------------
__global__ void k_conv_w(const float* __restrict__ W) {
    int idx = blockIdx.x * blockDim.x + threadIdx.x;    // 768*32 = 24576
    if (idx >= DK*32) return;
    int c   = idx & 31;
    int col = idx >> 5;
    int k0 = c*8;
    uint32_t h[4];
    #pragma unroll
    for (int j = 0; j < 4; j++) {
        __half a = __float2half_rn(W[(size_t)(k0 + 2*j    )*DK + col]);
        __half b = __float2half_rn(W[(size_t)(k0 + 2*j + 1)*DK + col]);
        h[j] = (uint32_t)__half_as_ushort(a) | ((uint32_t)__half_as_ushort(b) << 16);
    }
    size_t dst = (size_t)col*512 + (size_t)((c ^ (col & 7)) << 4);
    *(uint4*)((char*)g_bh + dst) = make_uint4(h[0], h[1], h[2], h[3]);
}

// ---------------------------------------------------------------------------
// Single-pass fp16 tensor-core GEMM: y = X @ W, fp32 accumulate.
// 1216 CTAs x 128 rows; 512 threads = 4x4 warps, warp tile 32x32.
// 6 N-tiles of 128, cp.async double-buffered B tiles (64KB each).
// smem: A 64KB | Btile[2] x 64KB = 192KB
// ---------------------------------------------------------------------------
#define GEMM_THREADS 512
#define OFF_B   65536u
#define B_TILE  65536u
#define SMEM_GEMM (65536 + 2*65536)   // 196608 B

__global__ void __launch_bounds__(GEMM_THREADS) k_gemm_mma(const float* __restrict__ X) {
    extern __shared__ char sm[];
    const int tid = threadIdx.x, lane = tid & 31, wid = tid >> 5;   // 0..15
    const int wm = wid & 3, wn = wid >> 2;     // 4 row-warps x 4 col-warps
    const size_t bm = blockIdx.x;

    const uint32_t sA = smem_u32(sm);

    // prologue: B tile 0 via cp.async (in flight), A converted inline
    #pragma unroll
    for (int u = 0; u < 8; u++) {
        int i = tid + u*512;                    // 0..4095
        cpa16(sA + OFF_B + (uint32_t)i*16u, (const char*)g_bh + (size_t)i*16);
    }
    CPA_COMMIT();
    {
        const float4* Xb = (const float4*)(X + bm*32768);
        #pragma unroll
        for (int u = 0; u < 16; u++) {
            int i = tid + u*512;
            int rr = i >> 6, c4 = i & 63;
            float4 v = Xb[i];
            union { __half h[4]; u64 u2; } hp;
            hp.h[0] = __float2half_rn(v.x);
            hp.h[1] = __float2half_rn(v.y);
            hp.h[2] = __float2half_rn(v.z);
            hp.h[3] = __float2half_rn(v.w);
            uint32_t base = (uint32_t)rr*512u
                          + ((((uint32_t)(c4 >> 1)) ^ (uint32_t)(rr & 7)) << 4)
                          + (uint32_t)((c4 & 1) * 8);
            *(u64*)(sm + base) = hp.u2;
        }
    }
    CPA_WAIT0();
    __syncthreads();

    const int rA    = wm*32 + (lane & 15);
    const int koffA = lane >> 4;
    const int rB    = wn*32 + (lane & 7) + ((lane >> 4) << 3);
    const int koffB = (lane >> 3) & 1;
    const int r0    = wm*32 + (lane >> 2);
    const uint32_t axor = (uint32_t)(rA & 7), bxor = (uint32_t)(rB & 7);
    const uint32_t aB = sA + (uint32_t)rA * 512;

    for (int nt = 0; nt < 6; nt++) {
        const int buf = nt & 1;
        // prefetch next B tile into the other buffer
        if (nt + 1 < 6) {
            uint32_t dst = sA + OFF_B + (uint32_t)(buf ^ 1) * B_TILE;
            const char* src = (const char*)g_bh + (size_t)(nt + 1) * B_TILE;
            #pragma unroll
            for (int u = 0; u < 8; u++) {
                int i = tid + u*512;
                cpa16(dst + (uint32_t)i*16u, src + (size_t)i*16);
            }
            CPA_COMMIT();
        }

        float acc[2][4][4];
        #pragma unroll
        for (int mi = 0; mi < 2; mi++)
            #pragma unroll
            for (int ni = 0; ni < 4; ni++)
                #pragma unroll
                for (int j = 0; j < 4; j++) acc[mi][ni][j] = 0.f;

        const uint32_t bB = sA + OFF_B + (uint32_t)buf * B_TILE + (uint32_t)rB * 512;

        #pragma unroll
        for (int kc = 0; kc < 16; kc++) {
            uint32_t ach = (((uint32_t)(kc*2 + koffA)) ^ axor) << 4;
            uint32_t bch = (((uint32_t)(kc*2 + koffB)) ^ bxor) << 4;
            uint32_t a0[4], a1[4], b0[4], b1[4];
            LDSM4(a0[0], a0[1], a0[2], a0[3], aB + ach);
            LDSM4(a1[0], a1[1], a1[2], a1[3], aB + 8192 + ach);
            LDSM4(b0[0], b0[1], b0[2], b0[3], bB + bch);
            LDSM4(b1[0], b1[1], b1[2], b1[3], bB + 8192 + bch);
            MMAF16(acc[0][0], a0, b0[0], b0[1]);
            MMAF16(acc[0][1], a0, b0[2], b0[3]);
            MMAF16(acc[0][2], a0, b1[0], b1[1]);
            MMAF16(acc[0][3], a0, b1[2], b1[3]);
            MMAF16(acc[1][0], a1, b0[0], b0[1]);
            MMAF16(acc[1][1], a1, b0[2], b0[3]);
            MMAF16(acc[1][2], a1, b1[0], b1[1]);
            MMAF16(acc[1][3], a1, b1[2], b1[3]);
        }

        // epilogue: write g_y (fp16) + BN stats (fp32, exact)
        #pragma unroll
        for (int mi = 0; mi < 2; mi++) {
            #pragma unroll
            for (int ni = 0; ni < 4; ni++) {
                int cb = wn*32 + ((ni >> 1) << 4) + ((ni & 1) << 3) + ((lane & 3) << 1);
                __half* p = g_y + (bm*128 + r0 + mi*16)*DK + nt*128 + cb;
                *(__half2*)p = __floats2half2_rn(acc[mi][ni][0], acc[mi][ni][1]);
                *(__half2*)(p + (size_t)8*DK) = __floats2half2_rn(acc[mi][ni][2], acc[mi][ni][3]);
            }
        }
        #pragma unroll
        for (int ni = 0; ni < 4; ni++) {
            float s0 = acc[0][ni][0] + acc[0][ni][2] + acc[1][ni][0] + acc[1][ni][2];
            float s1 = acc[0][ni][1] + acc[0][ni][3] + acc[1][ni][1] + acc[1][ni][3];
            float q0 = acc[0][ni][0]*acc[0][ni][0] + acc[0][ni][2]*acc[0][ni][2]
                     + acc[1][ni][0]*acc[1][ni][0] + acc[1][ni][2]*acc[1][ni][2];
            float q1 = acc[0][ni][1]*acc[0][ni][1] + acc[0][ni][3]*acc[0][ni][3]
                     + acc[1][ni][1]*acc[1][ni][1] + acc[1][ni][3]*acc[1][ni][3];
            #pragma unroll
            for (int off = 4; off < 32; off <<= 1) {
                s0 += __shfl_xor_sync(0xFFFFFFFFu, s0, off);
                s1 += __shfl_xor_sync(0xFFFFFFFFu, s1, off);
                q0 += __shfl_xor_sync(0xFFFFFFFFu, q0, off);
                q1 += __shfl_xor_sync(0xFFFFFFFFu, q1, off);
            }
            if (lane < 4) {
                int col = nt*128 + wn*32 + ((ni >> 1) << 4) + ((ni & 1) << 3) + lane*2;
                atomicAdd(&g_stats[col],         s0);
                atomicAdd(&g_stats[col + 1],     s1);
                atomicAdd(&g_stats[DK + col],    q0);
                atomicAdd(&g_stats[DK + col+1],  q1);
            }
        }

        if (nt + 1 < 6) CPA_WAIT0();
        __syncthreads();
    }
}

// ---------------------------------------------------------------------------
__global__ void k_fin_bn(const float* __restrict__ gamma, const float* __restrict__ beta) {
    int d = threadIdx.x;
    float inv = 1.0f / (float)MROWS;
    float mean = g_stats[d] * inv;
    float var  = g_stats[DK + d] * inv - mean*mean;
    float sc = gamma[d] * rsqrtf(var + 1e-5f);
    g_sb[d]      = sc;
    g_sb[DK + d] = beta[d] - mean*sc;
}

// ---------------------------------------------------------------------------
// Per-(n,t): z[c,w] = sum_{k,v} yhat[v, k*256+c] * An[k, c%8, v, w] + x[n,t,w,c]
// 4 tiles per block, cp.async DOUBLE-BUFFERED fp16 y tiles.
// Writes pre-activation z as fp16 to g_z (half the store traffic).
// smem: ybuf[2] x 29184B + A 36480B = 94848 B -> 2 CTAs/SM
// ---------------------------------------------------------------------------
#define YTILE_E (VNODES*DK)          // 14592 elements
#define YTILE_B (YTILE_E*2)          // 29184 bytes (fp16)
#define SMEM_CONTRACT (2*YTILE_B + 3*8*VNODES*20*4)   // 94848 B

__global__ void __launch_bounds__(256, 2) k_contract(const float* __restrict__ X) {
    extern __shared__ char smc[];
    float* Ash = (float*)(smc + 2*YTILE_B);
    const int tid = threadIdx.x;
    const size_t nt0 = (size_t)blockIdx.x * 4;
    const uint32_t sb = smem_u32(smc);

    for (int i = tid; i < 3*8*VNODES*20; i += 256) Ash[i] = g_An[i];
    {
        const char* src = (const char*)(g_y + nt0 * YTILE_E);
        for (int i = tid; i < YTILE_B/16; i += 256)
            cpa16(sb + (uint32_t)i*16u, src + (size_t)i*16);
        CPA_COMMIT();
    }

    const int c = tid, g = c & 7;
    float sc[3], of[3];
    #pragma unroll
    for (int k = 0; k < 3; k++) {
        sc[k] = g_sb[k*DM + c];
        of[k] = g_sb[DK + k*DM + c];
    }

    float s_tot = 0.f, q_tot = 0.f;

    for (int r = 0; r < 4; r++) {
        const size_t nt = nt0 + r;
        if (r < 3) {
            const char* src = (const char*)(g_y + (nt + 1) * YTILE_E);
            uint32_t dst = sb + (((r + 1) & 1) ? (uint32_t)YTILE_B : 0u);
            for (int i = tid; i < YTILE_B/16; i += 256)
                cpa16(dst + (uint32_t)i*16u, src + (size_t)i*16);
            CPA_COMMIT();
            CPA_WAIT1();
        } else {
            CPA_WAIT0();
        }
        __syncthreads();

        const __half* ysh = (const __half*)(smc + ((r & 1) ? YTILE_B : 0));

        u64 acc[10];
        #pragma unroll
        for (int p = 0; p < 10; p++) acc[p] = 0ull;
        #pragma unroll
        for (int k = 0; k < 3; k++) {
            const u64* Ab = (const u64*)(Ash + (size_t)((k*8 + g)*VNODES)*20);
            #pragma unroll
            for (int v = 0; v < VNODES; v++) {
                float yv = fmaf(__half2float(ysh[v*DK + k*DM + c]), sc[k], of[k]);
                u64 yp = pack2(yv, yv);
                const u64* ar = Ab + v*10;
                #pragma unroll
                for (int p = 0; p < 10; p++) ffma2(acc[p], yp, ar[p]);
            }
        }

        float z[20];
        #pragma unroll
        for (int p = 0; p < 10; p++) unpack2(acc[p], z[2*p], z[2*p+1]);

        const float* xb = X + nt * (size_t)(VNODES*DM) + c;
        __half* zb = g_z + nt * (size_t)(VNODES*DM) + c;
        #pragma unroll
        for (int w = 0; w < VNODES; w++) {
            float zv = z[w] + xb[(size_t)w * DM];
            s_tot += zv; q_tot += zv*zv;
            zb[(size_t)w * DM] = __float2half_rn(zv);
        }
        __syncthreads();
    }
    atomicAdd(&g_stats1[c], s_tot);
    atomicAdd(&g_stats1[DM + c], q_tot);
}

__global__ void k_fin_bn1(const float* __restrict__ gamma, const float* __restrict__ beta) {
    int d = threadIdx.x;
    float inv = 1.0f / (float)MROWS;
    float mean = g_stats1[d] * inv;
    float var  = g_stats1[DM + d] * inv - mean*mean;
    float sc = gamma[d] * rsqrtf(var + 1e-5f);
    g_sb1[d]      = sc;
    g_sb1[DM + d] = beta[d] - mean*sc;
}

// ---------------------------------------------------------------------------
// BN1 affine + ReLU: read fp16 z, write fp32 out. 8 elements per thread-iter.
// Scale/shift loaded as float4 vectors (NOT scalar — that was the R16 bug).
// ---------------------------------------------------------------------------
__global__ void k_relu(float* __restrict__ out) {
    size_t total8 = (size_t)MROWS * DM / 8;
    const uint4* z8 = (const uint4*)g_z;
    for (size_t i = (size_t)blockIdx.x * blockDim.x + threadIdx.x; i < total8;
         i += (size_t)gridDim.x * blockDim.x) {
        int c = (int)(i & 31) * 8;
        float4 sc0 = *(const float4*)&g_sb1[c];
        float4 sc1 = *(const float4*)&g_sb1[c + 4];
        float4 of0 = *(const float4*)&g_sb1[DM + c];
        float4 of1 = *(const float4*)&g_sb1[DM + c + 4];
        uint4 zv = z8[i];
        float2 f0 = __half22float2(*(const __half2*)&zv.x);
        float2 f1 = __half22float2(*(const __half2*)&zv.y);
        float2 f2 = __half22float2(*(const __half2*)&zv.z);
        float2 f3 = __half22float2(*(const __half2*)&zv.w);
        float4 o0, o1;
        o0.x = fmaxf(fmaf(f0.x, sc0.x, of0.x), 0.f);
        o0.y = fmaxf(fmaf(f0.y, sc0.y, of0.y), 0.f);
        o0.z = fmaxf(fmaf(f1.x, sc0.z, of0.z), 0.f);
        o0.w = fmaxf(fmaf(f1.y, sc0.w, of0.w), 0.f);
        o1.x = fmaxf(fmaf(f2.x, sc1.x, of1.x), 0.f);
        o1.y = fmaxf(fmaf(f2.y, sc1.y, of1.y), 0.f);
        o1.z = fmaxf(fmaf(f3.x, sc1.z, of1.z), 0.f);
        o1.w = fmaxf(fmaf(f3.y, sc1.w, of1.w), 0.f);
        float4* o4 = (float4*)(out + i*8);
        o4[0] = o0;
        o4[1] = o1;
    }
}

extern "C" void kernel_launch(void* const* d_in, const int* in_sizes, int n_in,
                              void* d_out, int out_size) {
    const float* x    = (const float*)d_in[0];
    const float* para = (const float*)d_in[1];
    const float* W    = (const float*)d_in[2];
    // d_in[3] linear_bias: cancels under training-mode BN (mean subtraction)
    const float* bng  = (const float*)d_in[4];
    const float* bnb  = (const float*)d_in[5];
    const float* bn1g = (const float*)d_in[6];
    const float* bn1b = (const float*)d_in[7];
    float* out = (float*)d_out;

    cudaFuncSetAttribute(k_contract, cudaFuncAttributeMaxDynamicSharedMemorySize,
                         SMEM_CONTRACT);
    cudaFuncSetAttribute(k_gemm_mma, cudaFuncAttributeMaxDynamicSharedMemorySize,
                         SMEM_GEMM);

    k_prep<<<1, 512>>>(para);
    k_conv_w<<<96, 256>>>(W);
    k_gemm_mma<<<MTILES, GEMM_THREADS, SMEM_GEMM>>>(x);
    k_fin_bn<<<1, DK>>>(bng, bnb);
    k_contract<<<NT/4, 256, SMEM_CONTRACT>>>(x);
    k_fin_bn1<<<1, DM>>>(bn1g, bn1b);
    k_relu<<<2048, 256>>>(out);
}